// round 1
// baseline (speedup 1.0000x reference)
#include <cuda_runtime.h>
#include <math.h>

#define HID   256
#define NB    4096
#define NN    204800
#define HF4   1024
// SCALE = sqrt(H / N_HEADS) = sqrt(32)
#define INV_SCALE 0.17677669529663687f

// ---------------- scratch (static device globals; no allocation) ----------------
__device__ float g_Qg[NB * HID];       // smiles @ wq + bq
__device__ float g_u [NB * HID];       // Qg @ wk^T
__device__ float g_wkT[HID * HID];
__device__ float g_c [NB];             // Qg . bk
__device__ float g_escore[NN];
__device__ float g_s [NB * HID];       // weighted segment sum of value_in
__device__ float g_dh[NB * HID];
__device__ float g_x1[NB * HID];       // after first LN
__device__ float g_h1[NB * HF4];
__device__ float g_h2[NB * HID];
__device__ int   g_segstart[NB + 1];

// ---------------- helpers ----------------
__device__ __forceinline__ float warp_sum(float v) {
#pragma unroll
    for (int o = 16; o; o >>= 1) v += __shfl_xor_sync(0xffffffffu, v, o);
    return v;
}

// 256-thread block sum; every thread returns the total.
__device__ __forceinline__ float block_sum_256(float v) {
    __shared__ float sh[8];
    int lane = threadIdx.x & 31, w = threadIdx.x >> 5;
    v = warp_sum(v);
    if (lane == 0) sh[w] = v;
    __syncthreads();
    float r = (lane < 8) ? sh[lane] : 0.f;
    r = warp_sum(r);
    __syncthreads();   // protect sh for a subsequent call
    return r;
}

// ---------------- kernels ----------------

// segment boundaries: batch is sorted; segstart[b] = first idx with batch[i] >= b
__global__ void seg_kernel(const int* __restrict__ batch) {
    int b = blockIdx.x * blockDim.x + threadIdx.x;
    if (b > NB) return;
    int lo = 0, hi = NN;
    while (lo < hi) { int mid = (lo + hi) >> 1; if (batch[mid] < b) lo = mid + 1; else hi = mid; }
    g_segstart[b] = lo;
}

__global__ void transpose_k(const float* __restrict__ in, float* __restrict__ out) {
    __shared__ float tile[32][33];
    int bx = blockIdx.x * 32, by = blockIdx.y * 32;
#pragma unroll
    for (int i = 0; i < 32; i += 8)
        tile[threadIdx.y + i][threadIdx.x] = in[(size_t)(by + threadIdx.y + i) * HID + bx + threadIdx.x];
    __syncthreads();
#pragma unroll
    for (int i = 0; i < 32; i += 8)
        out[(size_t)(bx + threadIdx.y + i) * HID + by + threadIdx.x] = tile[threadIdx.x][threadIdx.y + i];
}

// generic fp32 tiled GEMM: C[M,N] = A[M,K] @ B[K,N] (+bias) (+relu)
// BM=128 BN=64 BK=16, 256 threads, 8x4 per-thread microtile
template<bool BIAS, bool RELU>
__global__ __launch_bounds__(256)
void sgemm_kernel(const float* __restrict__ A, const float* __restrict__ B,
                  const float* __restrict__ bias, float* __restrict__ C,
                  int M, int N, int K)
{
    const int BM = 128, BN = 64, BK = 16, TM = 8, TN = 4;
    __shared__ float As[BK][BM + 1];
    __shared__ float Bs[BK][BN];
    const int tid = threadIdx.x;
    const int tx = tid % (BN / TN);   // 0..15
    const int ty = tid / (BN / TN);   // 0..15
    const int row0 = blockIdx.y * BM;
    const int col0 = blockIdx.x * BN;

    float acc[TM][TN];
#pragma unroll
    for (int m = 0; m < TM; m++)
#pragma unroll
        for (int n = 0; n < TN; n++) acc[m][n] = 0.f;

    for (int k0 = 0; k0 < K; k0 += BK) {
#pragma unroll
        for (int i = 0; i < (BM * BK) / 256; i++) {
            int idx = tid + i * 256;
            int r = idx / BK, c = idx % BK;
            As[c][r] = A[(size_t)(row0 + r) * K + k0 + c];
        }
#pragma unroll
        for (int i = 0; i < (BK * BN) / 256; i++) {
            int idx = tid + i * 256;
            int r = idx / BN, c = idx % BN;
            Bs[r][c] = B[(size_t)(k0 + r) * N + col0 + c];
        }
        __syncthreads();
#pragma unroll
        for (int kk = 0; kk < BK; kk++) {
            float a[TM], b[TN];
#pragma unroll
            for (int m = 0; m < TM; m++) a[m] = As[kk][ty * TM + m];
#pragma unroll
            for (int n = 0; n < TN; n++) b[n] = Bs[kk][tx * TN + n];
#pragma unroll
            for (int m = 0; m < TM; m++)
#pragma unroll
                for (int n = 0; n < TN; n++) acc[m][n] += a[m] * b[n];
        }
        __syncthreads();
    }
#pragma unroll
    for (int m = 0; m < TM; m++) {
        int row = row0 + ty * TM + m;
#pragma unroll
        for (int n = 0; n < TN; n++) {
            int col = col0 + tx * TN + n;
            float v = acc[m][n];
            if (BIAS) v += bias[col];
            if (RELU) v = fmaxf(v, 0.f);
            C[(size_t)row * N + col] = v;
        }
    }
}

// c[b] = Qg[b] . bk   (warp per row)
__global__ void cscore_kernel(const float* __restrict__ bk) {
    int gw = (blockIdx.x * blockDim.x + threadIdx.x) >> 5;
    int lane = threadIdx.x & 31;
    if (gw >= NB) return;
    float acc = 0.f;
#pragma unroll
    for (int t = 0; t < HID / 32; t++)
        acc += g_Qg[(size_t)gw * HID + lane + 32 * t] * bk[lane + 32 * t];
    acc = warp_sum(acc);
    if (lane == 0) g_c[gw] = acc;
}

// escore[n] = exp((key_in[n] . u[batch[n]] + c[batch[n]]) / SCALE)  (warp per node)
__global__ void score_kernel(const float* __restrict__ key, const int* __restrict__ batch) {
    int gw = (blockIdx.x * blockDim.x + threadIdx.x) >> 5;
    int lane = threadIdx.x & 31;
    if (gw >= NN) return;
    int b = batch[gw];
    const float* kp = key + (size_t)gw * HID;
    const float* up = g_u + (size_t)b  * HID;
    float acc = 0.f;
#pragma unroll
    for (int t = 0; t < HID / 32; t++)
        acc += kp[lane + 32 * t] * up[lane + 32 * t];
    acc = warp_sum(acc);
    if (lane == 0) g_escore[gw] = expf((acc + g_c[b]) * INV_SCALE);
}

// block per graph: denom, attention output, weighted sum of value rows
__global__ void attn_kernel(const float* __restrict__ value, float* __restrict__ att_out) {
    int b = blockIdx.x, t = threadIdx.x;
    int s0 = g_segstart[b], s1 = g_segstart[b + 1];
    float partial = 0.f;
    for (int n = s0 + t; n < s1; n += 256) partial += g_escore[n];
    float denom = block_sum_256(partial);
    float acc = 0.f;
    if (s1 > s0) {
        float invd = 1.f / denom;
        for (int n = s0 + t; n < s1; n += 256) att_out[n] = g_escore[n] / denom;
        for (int n = s0; n < s1; n++)
            acc += (g_escore[n] * invd) * value[(size_t)n * HID + t];
    }
    g_s[(size_t)b * HID + t] = acc;
}

// out = LN(x + r) * g + b   (block per row, 256 threads)
__global__ void ln_kernel(const float* __restrict__ x, const float* __restrict__ r,
                          const float* __restrict__ g, const float* __restrict__ b,
                          float* __restrict__ out) {
    int row = blockIdx.x, t = threadIdx.x;
    float v = x[(size_t)row * HID + t] + r[(size_t)row * HID + t];
    float mu = block_sum_256(v) * (1.f / HID);
    float d = v - mu;
    float var = block_sum_256(d * d) * (1.f / HID);
    out[(size_t)row * HID + t] = d * rsqrtf(var + 1e-5f) * g[t] + b[t];
}

// ---------------- launcher ----------------
extern "C" void kernel_launch(void* const* d_in, const int* in_sizes, int n_in,
                              void* d_out, int out_size) {
    const float* smiles   = (const float*)d_in[0];
    const float* key_in   = (const float*)d_in[1];
    const float* value_in = (const float*)d_in[2];
    const int*   batch    = (const int*)  d_in[3];
    const float* wq   = (const float*)d_in[4];
    const float* bq   = (const float*)d_in[5];
    const float* wk   = (const float*)d_in[6];
    const float* bk   = (const float*)d_in[7];
    const float* wv   = (const float*)d_in[8];
    const float* bv   = (const float*)d_in[9];
    const float* ln0g = (const float*)d_in[10];
    const float* ln0b = (const float*)d_in[11];
    const float* ln1g = (const float*)d_in[12];
    const float* ln1b = (const float*)d_in[13];
    const float* w1   = (const float*)d_in[14];
    const float* c1   = (const float*)d_in[15];
    const float* w2   = (const float*)d_in[16];
    const float* c2   = (const float*)d_in[17];

    float* out        = (float*)d_out;
    float* out_smiles = out;                      // [B, H]
    float* out_att    = out + (size_t)NB * HID;   // [N]

    float *Qg, *U, *WkT, *S, *Dh, *X1, *H1, *H2;
    cudaGetSymbolAddress((void**)&Qg,  g_Qg);
    cudaGetSymbolAddress((void**)&U,   g_u);
    cudaGetSymbolAddress((void**)&WkT, g_wkT);
    cudaGetSymbolAddress((void**)&S,   g_s);
    cudaGetSymbolAddress((void**)&Dh,  g_dh);
    cudaGetSymbolAddress((void**)&X1,  g_x1);
    cudaGetSymbolAddress((void**)&H1,  g_h1);
    cudaGetSymbolAddress((void**)&H2,  g_h2);

    // segment boundaries + wk transpose
    seg_kernel<<<(NB + 1 + 255) / 256, 256>>>(batch);
    transpose_k<<<dim3(HID / 32, HID / 32), dim3(32, 8)>>>(wk, WkT);

    // Qg = smiles @ wq + bq        [B,H]
    sgemm_kernel<true, false><<<dim3(HID / 64, NB / 128), 256>>>(smiles, wq, bq, Qg, NB, HID, HID);
    // c[b] = Qg[b] . bk
    cscore_kernel<<<NB / 8, 256>>>(bk);
    // u = Qg @ wk^T                 [B,H]
    sgemm_kernel<false, false><<<dim3(HID / 64, NB / 128), 256>>>(Qg, WkT, nullptr, U, NB, HID, HID);

    // per-node scores + exp
    score_kernel<<<NN / 8, 256>>>(key_in, batch);
    // per-graph softmax + attention output + weighted value sum
    attn_kernel<<<NB, 256>>>(value_in, out_att);

    // dh = s @ wv + bv              [B,H]
    sgemm_kernel<true, false><<<dim3(HID / 64, NB / 128), 256>>>(S, wv, bv, Dh, NB, HID, HID);
    // x1 = LN(smiles + dh)
    ln_kernel<<<NB, 256>>>(smiles, Dh, ln0g, ln0b, X1);

    // FFN
    sgemm_kernel<true, true ><<<dim3(HF4 / 64, NB / 128), 256>>>(X1, w1, c1, H1, NB, HF4, HID);
    sgemm_kernel<true, false><<<dim3(HID / 64, NB / 128), 256>>>(H1, w2, c2, H2, NB, HID, HF4);

    // out = LN(x1 + ffn)
    ln_kernel<<<NB, 256>>>(X1, H2, ln1g, ln1b, out_smiles);
}

// round 3
// speedup vs baseline: 1.5056x; 1.5056x over previous
#include <cuda_runtime.h>
#include <cuda_bf16.h>
#include <math.h>
#include <stdint.h>

#define HID   256
#define NB    4096
#define NN    204800
#define HF4   1024
#define INV_SCALE 0.17677669529663687f

// ---------------- scratch (static device globals; no allocation) ----------------
__device__ float g_Qg[NB * HID];
__device__ float g_u [NB * HID];
__device__ float g_wkT[HID * HID];
__device__ float g_c [NB];
__device__ float g_escore[NN];
__device__ float g_s [NB * HID];
__device__ float g_dh[NB * HID];
__device__ float g_x1[NB * HID];
__device__ float g_h1[NB * HF4];
__device__ float g_h2[NB * HID];
__device__ int   g_segstart[NB + 1];

// 16B-vector accessed: force alignment
__device__ __align__(256) __nv_bfloat16 g_ahi[NB * HF4];
__device__ __align__(256) __nv_bfloat16 g_alo[NB * HF4];
__device__ __align__(256) __nv_bfloat16 g_bhi[HID * HF4];
__device__ __align__(256) __nv_bfloat16 g_blo[HID * HF4];

// ---------------- helpers ----------------
__device__ __forceinline__ float warp_sum(float v) {
#pragma unroll
    for (int o = 16; o; o >>= 1) v += __shfl_xor_sync(0xffffffffu, v, o);
    return v;
}

__device__ __forceinline__ float block_sum_256(float v) {
    __shared__ float sh[8];
    int lane = threadIdx.x & 31, w = threadIdx.x >> 5;
    v = warp_sum(v);
    if (lane == 0) sh[w] = v;
    __syncthreads();
    float r = (lane < 8) ? sh[lane] : 0.f;
    r = warp_sum(r);
    __syncthreads();
    return r;
}

__device__ __forceinline__ uint32_t s2u(const void* p) {
    return (uint32_t)__cvta_generic_to_shared(p);
}

__device__ __forceinline__ void ldsm4(uint32_t& r0, uint32_t& r1, uint32_t& r2, uint32_t& r3, uint32_t addr) {
    asm volatile("ldmatrix.sync.aligned.m8n8.x4.shared.b16 {%0,%1,%2,%3}, [%4];"
                 : "=r"(r0), "=r"(r1), "=r"(r2), "=r"(r3) : "r"(addr));
}
__device__ __forceinline__ void ldsm4t(uint32_t& r0, uint32_t& r1, uint32_t& r2, uint32_t& r3, uint32_t addr) {
    asm volatile("ldmatrix.sync.aligned.m8n8.x4.trans.shared.b16 {%0,%1,%2,%3}, [%4];"
                 : "=r"(r0), "=r"(r1), "=r"(r2), "=r"(r3) : "r"(addr));
}
__device__ __forceinline__ void mma16816(float* c, const uint32_t* a, const uint32_t* b) {
    asm volatile("mma.sync.aligned.m16n8k16.row.col.f32.bf16.bf16.f32 "
                 "{%0,%1,%2,%3},{%4,%5,%6,%7},{%8,%9},{%0,%1,%2,%3};"
                 : "+f"(c[0]), "+f"(c[1]), "+f"(c[2]), "+f"(c[3])
                 : "r"(a[0]), "r"(a[1]), "r"(a[2]), "r"(a[3]), "r"(b[0]), "r"(b[1]));
}

// ---------------- small kernels ----------------
__global__ void seg_kernel(const int* __restrict__ batch) {
    int b = blockIdx.x * blockDim.x + threadIdx.x;
    if (b > NB) return;
    int lo = 0, hi = NN;
    while (lo < hi) { int mid = (lo + hi) >> 1; if (batch[mid] < b) lo = mid + 1; else hi = mid; }
    g_segstart[b] = lo;
}

__global__ void transpose_k(const float* __restrict__ in, float* __restrict__ out) {
    __shared__ float tile[32][33];
    int bx = blockIdx.x * 32, by = blockIdx.y * 32;
#pragma unroll
    for (int i = 0; i < 32; i += 8)
        tile[threadIdx.y + i][threadIdx.x] = in[(size_t)(by + threadIdx.y + i) * HID + bx + threadIdx.x];
    __syncthreads();
#pragma unroll
    for (int i = 0; i < 32; i += 8)
        out[(size_t)(bx + threadIdx.y + i) * HID + by + threadIdx.x] = tile[threadIdx.x][threadIdx.y + i];
}

// fp32 -> (hi, lo) bf16 split; 4 elements per thread
__global__ void cvt_kernel(const float* __restrict__ in, __nv_bfloat16* __restrict__ hi,
                           __nv_bfloat16* __restrict__ lo, int n4) {
    int i = blockIdx.x * blockDim.x + threadIdx.x;
    if (i >= n4) return;
    float4 v = ((const float4*)in)[i];
    __nv_bfloat16 h0 = __float2bfloat16(v.x);
    __nv_bfloat16 h1 = __float2bfloat16(v.y);
    __nv_bfloat16 h2 = __float2bfloat16(v.z);
    __nv_bfloat16 h3 = __float2bfloat16(v.w);
    __nv_bfloat16 l0 = __float2bfloat16(v.x - __bfloat162float(h0));
    __nv_bfloat16 l1 = __float2bfloat16(v.y - __bfloat162float(h1));
    __nv_bfloat16 l2 = __float2bfloat16(v.z - __bfloat162float(h2));
    __nv_bfloat16 l3 = __float2bfloat16(v.w - __bfloat162float(h3));
    __nv_bfloat162* hp = (__nv_bfloat162*)hi;
    __nv_bfloat162* lp = (__nv_bfloat162*)lo;
    hp[2 * i]     = __halves2bfloat162(h0, h1);
    hp[2 * i + 1] = __halves2bfloat162(h2, h3);
    lp[2 * i]     = __halves2bfloat162(l0, l1);
    lp[2 * i + 1] = __halves2bfloat162(l2, l3);
}

// ---------------- tensor-core split-bf16 GEMM ----------------
// C[M,N] = (Ahi+Alo)[M,K] @ (Bhi+Blo)[K,N]  (+bias) (+relu), fp32 accumulate
// BM=128 BN=64 BK=32, 256 threads (8 warps: 4x2), warp tile 32x32
#define ASTR 40   // bf16 units per A smem row (32 + 8 pad) => 80B stride
#define BSTR 72   // bf16 units per B smem row (64 + 8 pad) => 144B stride

template<bool BIAS, bool RELU>
__global__ __launch_bounds__(256)
void bgemm_kernel(const __nv_bfloat16* __restrict__ Ahi, const __nv_bfloat16* __restrict__ Alo,
                  const __nv_bfloat16* __restrict__ Bhi, const __nv_bfloat16* __restrict__ Blo,
                  const float* __restrict__ bias, float* __restrict__ C,
                  int M, int N, int K)
{
    __shared__ __align__(16) __nv_bfloat16 sAh[128 * ASTR], sAl[128 * ASTR];
    __shared__ __align__(16) __nv_bfloat16 sBh[32 * BSTR],  sBl[32 * BSTR];

    const int tid  = threadIdx.x;
    const int lane = tid & 31, wid = tid >> 5;
    const int wm = wid >> 1, wn = wid & 1;
    const int row0 = blockIdx.y * 128, col0 = blockIdx.x * 64;

    const int ar = tid >> 2, ac = (tid & 3) * 8;   // A: rows ar, ar+64
    const int br = tid >> 3, bc = (tid & 7) * 8;   // B: 32 rows x 64 cols

    float acc[2][4][4];
#pragma unroll
    for (int mi = 0; mi < 2; mi++)
#pragma unroll
        for (int nj = 0; nj < 4; nj++)
#pragma unroll
            for (int q = 0; q < 4; q++) acc[mi][nj][q] = 0.f;

    uint4 pAh0, pAh1, pAl0, pAl1, pBh, pBl;

    const size_t aoff0 = (size_t)(row0 + ar) * K + ac;
    const size_t aoff1 = aoff0 + (size_t)64 * K;
    const size_t boffg = (size_t)br * N + col0 + bc;

    pAh0 = *(const uint4*)(Ahi + aoff0);
    pAh1 = *(const uint4*)(Ahi + aoff1);
    pAl0 = *(const uint4*)(Alo + aoff0);
    pAl1 = *(const uint4*)(Alo + aoff1);
    pBh  = *(const uint4*)(Bhi + boffg);
    pBl  = *(const uint4*)(Blo + boffg);

    const uint32_t sAh_u = s2u(sAh), sAl_u = s2u(sAl), sBh_u = s2u(sBh), sBl_u = s2u(sBl);
    const int a_lrow = wm * 32 + (lane & 15);
    const int a_lcol = ((lane >> 4) & 1) * 8;
    const int b_lrow = (lane & 7) + ((lane >> 3) & 1) * 8;
    const int b_lcol = wn * 32 + ((lane >> 4) & 1) * 8;

    const int NT = K / 32;
    for (int kt = 0; kt < NT; kt++) {
        *(uint4*)&sAh[ar * ASTR + ac]        = pAh0;
        *(uint4*)&sAh[(ar + 64) * ASTR + ac] = pAh1;
        *(uint4*)&sAl[ar * ASTR + ac]        = pAl0;
        *(uint4*)&sAl[(ar + 64) * ASTR + ac] = pAl1;
        *(uint4*)&sBh[br * BSTR + bc]        = pBh;
        *(uint4*)&sBl[br * BSTR + bc]        = pBl;
        __syncthreads();

        if (kt + 1 < NT) {
            size_t ka = (size_t)(kt + 1) * 32;
            pAh0 = *(const uint4*)(Ahi + aoff0 + ka);
            pAh1 = *(const uint4*)(Ahi + aoff1 + ka);
            pAl0 = *(const uint4*)(Alo + aoff0 + ka);
            pAl1 = *(const uint4*)(Alo + aoff1 + ka);
            pBh  = *(const uint4*)(Bhi + boffg + ka * N);
            pBl  = *(const uint4*)(Blo + boffg + ka * N);
        }

#pragma unroll
        for (int ks = 0; ks < 2; ks++) {
            uint32_t ah[2][4], al[2][4], bh[4][2], bl[4][2];
#pragma unroll
            for (int mi = 0; mi < 2; mi++) {
                uint32_t aoff = (uint32_t)(((a_lrow + mi * 16) * ASTR + ks * 16 + a_lcol) * 2);
                ldsm4(ah[mi][0], ah[mi][1], ah[mi][2], ah[mi][3], sAh_u + aoff);
                ldsm4(al[mi][0], al[mi][1], al[mi][2], al[mi][3], sAl_u + aoff);
            }
#pragma unroll
            for (int nj2 = 0; nj2 < 2; nj2++) {
                uint32_t boff = (uint32_t)(((ks * 16 + b_lrow) * BSTR + b_lcol + nj2 * 16) * 2);
                uint32_t t0, t1, t2, t3;
                ldsm4t(t0, t1, t2, t3, sBh_u + boff);
                bh[nj2 * 2][0] = t0; bh[nj2 * 2][1] = t1;
                bh[nj2 * 2 + 1][0] = t2; bh[nj2 * 2 + 1][1] = t3;
                ldsm4t(t0, t1, t2, t3, sBl_u + boff);
                bl[nj2 * 2][0] = t0; bl[nj2 * 2][1] = t1;
                bl[nj2 * 2 + 1][0] = t2; bl[nj2 * 2 + 1][1] = t3;
            }
#pragma unroll
            for (int mi = 0; mi < 2; mi++)
#pragma unroll
                for (int nj = 0; nj < 4; nj++) {
                    mma16816(acc[mi][nj], ah[mi], bh[nj]);
                    mma16816(acc[mi][nj], ah[mi], bl[nj]);
                    mma16816(acc[mi][nj], al[mi], bh[nj]);
                }
        }
        __syncthreads();
    }

#pragma unroll
    for (int mi = 0; mi < 2; mi++) {
        int r = row0 + wm * 32 + mi * 16 + (lane >> 2);
#pragma unroll
        for (int nj = 0; nj < 4; nj++) {
            int c = col0 + wn * 32 + nj * 8 + (lane & 3) * 2;
            float b0 = 0.f, b1 = 0.f;
            if (BIAS) { b0 = bias[c]; b1 = bias[c + 1]; }
            float v00 = acc[mi][nj][0] + b0, v01 = acc[mi][nj][1] + b1;
            float v10 = acc[mi][nj][2] + b0, v11 = acc[mi][nj][3] + b1;
            if (RELU) {
                v00 = fmaxf(v00, 0.f); v01 = fmaxf(v01, 0.f);
                v10 = fmaxf(v10, 0.f); v11 = fmaxf(v11, 0.f);
            }
            *(float2*)&C[(size_t)r * N + c]       = make_float2(v00, v01);
            *(float2*)&C[(size_t)(r + 8) * N + c] = make_float2(v10, v11);
        }
    }
}

// ---------------- attention pieces ----------------
__global__ void cscore_kernel(const float* __restrict__ bk) {
    int gw = (blockIdx.x * blockDim.x + threadIdx.x) >> 5;
    int lane = threadIdx.x & 31;
    if (gw >= NB) return;
    float acc = 0.f;
#pragma unroll
    for (int t = 0; t < HID / 32; t++)
        acc += g_Qg[(size_t)gw * HID + lane + 32 * t] * bk[lane + 32 * t];
    acc = warp_sum(acc);
    if (lane == 0) g_c[gw] = acc;
}

__global__ void score_kernel(const float* __restrict__ key, const int* __restrict__ batch) {
    int gw = (blockIdx.x * blockDim.x + threadIdx.x) >> 5;
    int lane = threadIdx.x & 31;
    if (gw >= NN) return;
    int b = batch[gw];
    const float* kp = key + (size_t)gw * HID;
    const float* up = g_u + (size_t)b  * HID;
    float acc = 0.f;
#pragma unroll
    for (int t = 0; t < HID / 32; t++)
        acc += kp[lane + 32 * t] * up[lane + 32 * t];
    acc = warp_sum(acc);
    if (lane == 0) g_escore[gw] = expf((acc + g_c[b]) * INV_SCALE);
}

__global__ void attn_kernel(const float* __restrict__ value, float* __restrict__ att_out) {
    int b = blockIdx.x, t = threadIdx.x;
    int s0 = g_segstart[b], s1 = g_segstart[b + 1];
    float partial = 0.f;
    for (int n = s0 + t; n < s1; n += 256) partial += g_escore[n];
    float denom = block_sum_256(partial);
    float acc = 0.f;
    if (s1 > s0) {
        float invd = 1.f / denom;
        for (int n = s0 + t; n < s1; n += 256) att_out[n] = g_escore[n] * invd;
#pragma unroll 4
        for (int n = s0; n < s1; n++)
            acc += (g_escore[n] * invd) * value[(size_t)n * HID + t];
    }
    g_s[(size_t)b * HID + t] = acc;
}

__global__ void ln_kernel(const float* __restrict__ x, const float* __restrict__ r,
                          const float* __restrict__ g, const float* __restrict__ b,
                          float* __restrict__ out) {
    int row = blockIdx.x, t = threadIdx.x;
    float v = x[(size_t)row * HID + t] + r[(size_t)row * HID + t];
    float mu = block_sum_256(v) * (1.f / HID);
    float d = v - mu;
    float var = block_sum_256(d * d) * (1.f / HID);
    out[(size_t)row * HID + t] = d * rsqrtf(var + 1e-5f) * g[t] + b[t];
}

// ---------------- launcher ----------------
extern "C" void kernel_launch(void* const* d_in, const int* in_sizes, int n_in,
                              void* d_out, int out_size) {
    const float* smiles   = (const float*)d_in[0];
    const float* key_in   = (const float*)d_in[1];
    const float* value_in = (const float*)d_in[2];
    const int*   batch    = (const int*)  d_in[3];
    const float* wq   = (const float*)d_in[4];
    const float* bq   = (const float*)d_in[5];
    const float* wk   = (const float*)d_in[6];
    const float* bk   = (const float*)d_in[7];
    const float* wv   = (const float*)d_in[8];
    const float* bv   = (const float*)d_in[9];
    const float* ln0g = (const float*)d_in[10];
    const float* ln0b = (const float*)d_in[11];
    const float* ln1g = (const float*)d_in[12];
    const float* ln1b = (const float*)d_in[13];
    const float* w1   = (const float*)d_in[14];
    const float* c1   = (const float*)d_in[15];
    const float* w2   = (const float*)d_in[16];
    const float* c2   = (const float*)d_in[17];

    float* out        = (float*)d_out;
    float* out_smiles = out;
    float* out_att    = out + (size_t)NB * HID;

    float *Qg, *U, *WkT, *S, *Dh, *X1, *H1, *H2;
    __nv_bfloat16 *Ahi, *Alo, *Bhi, *Blo;
    cudaGetSymbolAddress((void**)&Qg,  g_Qg);
    cudaGetSymbolAddress((void**)&U,   g_u);
    cudaGetSymbolAddress((void**)&WkT, g_wkT);
    cudaGetSymbolAddress((void**)&S,   g_s);
    cudaGetSymbolAddress((void**)&Dh,  g_dh);
    cudaGetSymbolAddress((void**)&X1,  g_x1);
    cudaGetSymbolAddress((void**)&H1,  g_h1);
    cudaGetSymbolAddress((void**)&H2,  g_h2);
    cudaGetSymbolAddress((void**)&Ahi, g_ahi);
    cudaGetSymbolAddress((void**)&Alo, g_alo);
    cudaGetSymbolAddress((void**)&Bhi, g_bhi);
    cudaGetSymbolAddress((void**)&Blo, g_blo);

    auto cvtA = [&](const float* src, int n) {
        cvt_kernel<<<(n / 4 + 255) / 256, 256>>>(src, Ahi, Alo, n / 4);
    };
    auto cvtB = [&](const float* src, int n) {
        cvt_kernel<<<(n / 4 + 255) / 256, 256>>>(src, Bhi, Blo, n / 4);
    };

    seg_kernel<<<(NB + 1 + 255) / 256, 256>>>(batch);
    transpose_k<<<dim3(HID / 32, HID / 32), dim3(32, 8)>>>(wk, WkT);

    // Qg = smiles @ wq + bq
    cvtA(smiles, NB * HID);
    cvtB(wq, HID * HID);
    bgemm_kernel<true, false><<<dim3(HID / 64, NB / 128), 256>>>(Ahi, Alo, Bhi, Blo, bq, Qg, NB, HID, HID);
    cscore_kernel<<<NB / 8, 256>>>(bk);

    // U = Qg @ wk^T
    cvtA(Qg, NB * HID);
    cvtB(WkT, HID * HID);
    bgemm_kernel<false, false><<<dim3(HID / 64, NB / 128), 256>>>(Ahi, Alo, Bhi, Blo, nullptr, U, NB, HID, HID);

    // per-node scores, per-graph softmax + weighted value sum
    score_kernel<<<NN / 8, 256>>>(key_in, batch);
    attn_kernel<<<NB, 256>>>(value_in, out_att);

    // Dh = S @ wv + bv
    cvtA(S, NB * HID);
    cvtB(wv, HID * HID);
    bgemm_kernel<true, false><<<dim3(HID / 64, NB / 128), 256>>>(Ahi, Alo, Bhi, Blo, bv, Dh, NB, HID, HID);
    ln_kernel<<<NB, 256>>>(smiles, Dh, ln0g, ln0b, X1);

    // FFN
    cvtA(X1, NB * HID);
    cvtB(w1, HID * HF4);
    bgemm_kernel<true, true ><<<dim3(HF4 / 64, NB / 128), 256>>>(Ahi, Alo, Bhi, Blo, c1, H1, NB, HF4, HID);
    cvtA(H1, NB * HF4);
    cvtB(w2, HF4 * HID);
    bgemm_kernel<true, false><<<dim3(HID / 64, NB / 128), 256>>>(Ahi, Alo, Bhi, Blo, c2, H2, NB, HID, HF4);

    ln_kernel<<<NB, 256>>>(X1, H2, ln1g, ln1b, out_smiles);
}

// round 5
// speedup vs baseline: 1.7078x; 1.1343x over previous
#include <cuda_runtime.h>
#include <cuda_bf16.h>
#include <math.h>
#include <stdint.h>

#define HID   256
#define NB    4096
#define NN    204800
#define HF4   1024
#define INV_SCALE 0.17677669529663687f

// ---------------- scratch (static device globals; no allocation) ----------------
__device__ float g_u [NB * HID];       // per-graph score vector
__device__ float g_wkT[HID * HID];
__device__ float g_M  [HID * HID];     // wq @ wk^T
__device__ float g_rvec[HID];          // bq @ wk^T
__device__ float g_wcvec[HID];         // wq @ bk
__device__ float g_c0;                 // bq . bk
__device__ float g_c [NB];             // per-graph score constant
__device__ float g_escore[NN];
__device__ float g_s [NB * HID];       // weighted segment sum of value_in
__device__ float g_dh[NB * HID];
__device__ float g_x1[NB * HID];
__device__ float g_h1[NB * HF4];
__device__ float g_h2[NB * HID];
__device__ int   g_segstart[NB + 1];

// ---------------- helpers ----------------
__device__ __forceinline__ float warp_sum(float v) {
#pragma unroll
    for (int o = 16; o; o >>= 1) v += __shfl_xor_sync(0xffffffffu, v, o);
    return v;
}

__device__ __forceinline__ float block_sum_256(float v) {
    __shared__ float sh[8];
    int lane = threadIdx.x & 31, w = threadIdx.x >> 5;
    v = warp_sum(v);
    if (lane == 0) sh[w] = v;
    __syncthreads();
    float r = (lane < 8) ? sh[lane] : 0.f;
    r = warp_sum(r);
    __syncthreads();
    return r;
}

__device__ __forceinline__ uint32_t s2u(const void* p) {
    return (uint32_t)__cvta_generic_to_shared(p);
}

__device__ __forceinline__ void ldsm4(uint32_t& r0, uint32_t& r1, uint32_t& r2, uint32_t& r3, uint32_t addr) {
    asm volatile("ldmatrix.sync.aligned.m8n8.x4.shared.b16 {%0,%1,%2,%3}, [%4];"
                 : "=r"(r0), "=r"(r1), "=r"(r2), "=r"(r3) : "r"(addr));
}
__device__ __forceinline__ void ldsm4t(uint32_t& r0, uint32_t& r1, uint32_t& r2, uint32_t& r3, uint32_t addr) {
    asm volatile("ldmatrix.sync.aligned.m8n8.x4.trans.shared.b16 {%0,%1,%2,%3}, [%4];"
                 : "=r"(r0), "=r"(r1), "=r"(r2), "=r"(r3) : "r"(addr));
}
__device__ __forceinline__ void mma16816(float* c, const uint32_t* a, const uint32_t* b) {
    asm volatile("mma.sync.aligned.m16n8k16.row.col.f32.bf16.bf16.f32 "
                 "{%0,%1,%2,%3},{%4,%5,%6,%7},{%8,%9},{%0,%1,%2,%3};"
                 : "+f"(c[0]), "+f"(c[1]), "+f"(c[2]), "+f"(c[3])
                 : "r"(a[0]), "r"(a[1]), "r"(a[2]), "r"(a[3]), "r"(b[0]), "r"(b[1]));
}

// split a float4 into hi/lo bf16 pairs packed as 8B each
__device__ __forceinline__ void split4(float4 v, uint2& h, uint2& l) {
    __nv_bfloat16 h0 = __float2bfloat16(v.x), h1 = __float2bfloat16(v.y);
    __nv_bfloat16 h2 = __float2bfloat16(v.z), h3 = __float2bfloat16(v.w);
    __nv_bfloat16 l0 = __float2bfloat16(v.x - __bfloat162float(h0));
    __nv_bfloat16 l1 = __float2bfloat16(v.y - __bfloat162float(h1));
    __nv_bfloat16 l2 = __float2bfloat16(v.z - __bfloat162float(h2));
    __nv_bfloat16 l3 = __float2bfloat16(v.w - __bfloat162float(h3));
    union { __nv_bfloat162 b2[2]; uint2 u; } th, tl;
    th.b2[0] = __halves2bfloat162(h0, h1); th.b2[1] = __halves2bfloat162(h2, h3);
    tl.b2[0] = __halves2bfloat162(l0, l1); tl.b2[1] = __halves2bfloat162(l2, l3);
    h = th.u; l = tl.u;
}

// ---------------- small kernels ----------------
__global__ void seg_kernel(const int* __restrict__ batch) {
    int b = blockIdx.x * blockDim.x + threadIdx.x;
    if (b > NB) return;
    int lo = 0, hi = NN;
    while (lo < hi) { int mid = (lo + hi) >> 1; if (batch[mid] < b) lo = mid + 1; else hi = mid; }
    g_segstart[b] = lo;
}

__global__ void transpose_k(const float* __restrict__ in, float* __restrict__ out) {
    __shared__ float tile[32][33];
    int bx = blockIdx.x * 32, by = blockIdx.y * 32;
#pragma unroll
    for (int i = 0; i < 32; i += 8)
        tile[threadIdx.y + i][threadIdx.x] = in[(size_t)(by + threadIdx.y + i) * HID + bx + threadIdx.x];
    __syncthreads();
#pragma unroll
    for (int i = 0; i < 32; i += 8)
        out[(size_t)(bx + threadIdx.y + i) * HID + by + threadIdx.x] = tile[threadIdx.x][threadIdx.y + i];
}

// wcvec = wq @ bk ; rvec = bq @ wk^T ; c0 = bq . bk   (warp per row)
__global__ void prep_kernel(const float* __restrict__ wq, const float* __restrict__ wk,
                            const float* __restrict__ bq, const float* __restrict__ bk) {
    int gw = (blockIdx.x * blockDim.x + threadIdx.x) >> 5;
    int lane = threadIdx.x & 31;
    if (gw > 2 * HID) return;
    const float* rowp;
    const float* vecp;
    if (gw < HID)            { rowp = wq + (size_t)gw * HID;          vecp = bk; }
    else if (gw < 2 * HID)   { rowp = wk + (size_t)(gw - HID) * HID;  vecp = bq; }
    else                     { rowp = bq;                             vecp = bk; }
    float acc = 0.f;
#pragma unroll
    for (int t = 0; t < HID / 32; t++)
        acc += rowp[lane + 32 * t] * vecp[lane + 32 * t];
    acc = warp_sum(acc);
    if (lane == 0) {
        if (gw < HID)          g_wcvec[gw] = acc;
        else if (gw < 2 * HID) g_rvec[gw - HID] = acc;
        else                   g_c0 = acc;
    }
}

// c[b] = smiles[b] . wcvec + c0   (warp per graph)
__global__ void c_kernel(const float* __restrict__ smiles) {
    int gw = (blockIdx.x * blockDim.x + threadIdx.x) >> 5;
    int lane = threadIdx.x & 31;
    if (gw >= NB) return;
    const float* sp = smiles + (size_t)gw * HID;
    float acc = 0.f;
#pragma unroll
    for (int t = 0; t < HID / 32; t++)
        acc += sp[lane + 32 * t] * g_wcvec[lane + 32 * t];
    acc = warp_sum(acc);
    if (lane == 0) g_c[gw] = acc + g_c0;
}

// ---------------- tensor-core split-bf16 GEMM, fused fp32 load/convert ----------------
// C[M,N] = A[M,K] @ B[K,N] (+bias) (+relu); fp32 in/out, split-bf16 mma internally
// BM=128 BN=64 BK=32, 256 threads (8 warps 4x2), warp tile 32x32
#define ASTR 40   // bf16 units per A smem row (32 + 8 pad)
#define BSTR 72   // bf16 units per B smem row (64 + 8 pad)

template<bool BIAS, bool RELU>
__global__ __launch_bounds__(256)
void bgemm_kernel(const float* __restrict__ A, const float* __restrict__ B,
                  const float* __restrict__ bias, float* __restrict__ C,
                  int M, int N, int K)
{
    __shared__ __align__(16) __nv_bfloat16 sAh[128 * ASTR], sAl[128 * ASTR];
    __shared__ __align__(16) __nv_bfloat16 sBh[32 * BSTR],  sBl[32 * BSTR];

    const int tid  = threadIdx.x;
    const int lane = tid & 31, wid = tid >> 5;
    const int wm = wid >> 1, wn = wid & 1;
    const int row0 = blockIdx.y * 128, col0 = blockIdx.x * 64;

    float acc[2][4][4];
#pragma unroll
    for (int mi = 0; mi < 2; mi++)
#pragma unroll
        for (int nj = 0; nj < 4; nj++)
#pragma unroll
            for (int q = 0; q < 4; q++) acc[mi][nj][q] = 0.f;

    // A: 128x32 fp32 = 1024 float4, 4/thread; B: 32x64 = 512 float4, 2/thread
    int a_r[4], a_c[4], b_r[2], b_c[2];
    size_t a_off[4], b_off[2];
#pragma unroll
    for (int i = 0; i < 4; i++) {
        int idx = tid + i * 256;
        a_r[i] = idx >> 3; a_c[i] = (idx & 7) * 4;
        a_off[i] = (size_t)(row0 + a_r[i]) * K + a_c[i];
    }
#pragma unroll
    for (int i = 0; i < 2; i++) {
        int idx = tid + i * 256;
        b_r[i] = idx >> 4; b_c[i] = (idx & 15) * 4;
        b_off[i] = (size_t)b_r[i] * N + col0 + b_c[i];
    }

    float4 pA[4], pB[2];
#pragma unroll
    for (int i = 0; i < 4; i++) pA[i] = *(const float4*)(A + a_off[i]);
#pragma unroll
    for (int i = 0; i < 2; i++) pB[i] = *(const float4*)(B + b_off[i]);

    const uint32_t sAh_u = s2u(sAh), sAl_u = s2u(sAl), sBh_u = s2u(sBh), sBl_u = s2u(sBl);
    const int a_lrow = wm * 32 + (lane & 15);
    const int a_lcol = ((lane >> 4) & 1) * 8;
    const int b_lrow = (lane & 7) + ((lane >> 3) & 1) * 8;
    const int b_lcol = wn * 32 + ((lane >> 4) & 1) * 8;

    const int NT = K / 32;
    for (int kt = 0; kt < NT; kt++) {
#pragma unroll
        for (int i = 0; i < 4; i++) {
            uint2 h, l; split4(pA[i], h, l);
            *(uint2*)&sAh[a_r[i] * ASTR + a_c[i]] = h;
            *(uint2*)&sAl[a_r[i] * ASTR + a_c[i]] = l;
        }
#pragma unroll
        for (int i = 0; i < 2; i++) {
            uint2 h, l; split4(pB[i], h, l);
            *(uint2*)&sBh[b_r[i] * BSTR + b_c[i]] = h;
            *(uint2*)&sBl[b_r[i] * BSTR + b_c[i]] = l;
        }
        __syncthreads();

        if (kt + 1 < NT) {
#pragma unroll
            for (int i = 0; i < 4; i++) pA[i] = *(const float4*)(A + a_off[i] + (size_t)(kt + 1) * 32);
#pragma unroll
            for (int i = 0; i < 2; i++) pB[i] = *(const float4*)(B + b_off[i] + (size_t)(kt + 1) * 32 * N);
        }

#pragma unroll
        for (int ks = 0; ks < 2; ks++) {
            uint32_t ah[2][4], al[2][4], bh[4][2], bl[4][2];
#pragma unroll
            for (int mi = 0; mi < 2; mi++) {
                uint32_t aoff = (uint32_t)(((a_lrow + mi * 16) * ASTR + ks * 16 + a_lcol) * 2);
                ldsm4(ah[mi][0], ah[mi][1], ah[mi][2], ah[mi][3], sAh_u + aoff);
                ldsm4(al[mi][0], al[mi][1], al[mi][2], al[mi][3], sAl_u + aoff);
            }
#pragma unroll
            for (int nj2 = 0; nj2 < 2; nj2++) {
                uint32_t boff = (uint32_t)(((ks * 16 + b_lrow) * BSTR + b_lcol + nj2 * 16) * 2);
                uint32_t t0, t1, t2, t3;
                ldsm4t(t0, t1, t2, t3, sBh_u + boff);
                bh[nj2 * 2][0] = t0; bh[nj2 * 2][1] = t1;
                bh[nj2 * 2 + 1][0] = t2; bh[nj2 * 2 + 1][1] = t3;
                ldsm4t(t0, t1, t2, t3, sBl_u + boff);
                bl[nj2 * 2][0] = t0; bl[nj2 * 2][1] = t1;
                bl[nj2 * 2 + 1][0] = t2; bl[nj2 * 2 + 1][1] = t3;
            }
#pragma unroll
            for (int mi = 0; mi < 2; mi++)
#pragma unroll
                for (int nj = 0; nj < 4; nj++) {
                    mma16816(acc[mi][nj], ah[mi], bh[nj]);
                    mma16816(acc[mi][nj], ah[mi], bl[nj]);
                    mma16816(acc[mi][nj], al[mi], bh[nj]);
                }
        }
        __syncthreads();
    }

#pragma unroll
    for (int mi = 0; mi < 2; mi++) {
        int r = row0 + wm * 32 + mi * 16 + (lane >> 2);
#pragma unroll
        for (int nj = 0; nj < 4; nj++) {
            int c = col0 + wn * 32 + nj * 8 + (lane & 3) * 2;
            float b0 = 0.f, b1 = 0.f;
            if (BIAS) { b0 = bias[c]; b1 = bias[c + 1]; }
            float v00 = acc[mi][nj][0] + b0, v01 = acc[mi][nj][1] + b1;
            float v10 = acc[mi][nj][2] + b0, v11 = acc[mi][nj][3] + b1;
            if (RELU) {
                v00 = fmaxf(v00, 0.f); v01 = fmaxf(v01, 0.f);
                v10 = fmaxf(v10, 0.f); v11 = fmaxf(v11, 0.f);
            }
            *(float2*)&C[(size_t)r * N + c]       = make_float2(v00, v01);
            *(float2*)&C[(size_t)(r + 8) * N + c] = make_float2(v10, v11);
        }
    }
}

// ---------------- attention pieces ----------------
__global__ void score_kernel(const float* __restrict__ key, const int* __restrict__ batch) {
    int gw = (blockIdx.x * blockDim.x + threadIdx.x) >> 5;
    int lane = threadIdx.x & 31;
    if (gw >= NN) return;
    int b = batch[gw];
    const float* kp = key + (size_t)gw * HID;
    const float* up = g_u + (size_t)b  * HID;
    float acc = 0.f;
#pragma unroll
    for (int t = 0; t < HID / 32; t++)
        acc += kp[lane + 32 * t] * up[lane + 32 * t];
    acc = warp_sum(acc);
    if (lane == 0) g_escore[gw] = expf((acc + g_c[b]) * INV_SCALE);
}

__global__ void attn_kernel(const float* __restrict__ value, float* __restrict__ att_out) {
    int b = blockIdx.x, t = threadIdx.x;
    int s0 = g_segstart[b], s1 = g_segstart[b + 1];
    float partial = 0.f;
    for (int n = s0 + t; n < s1; n += 256) partial += g_escore[n];
    float denom = block_sum_256(partial);
    float acc = 0.f;
    if (s1 > s0) {
        float invd = 1.f / denom;
        for (int n = s0 + t; n < s1; n += 256) att_out[n] = g_escore[n] * invd;
#pragma unroll 4
        for (int n = s0; n < s1; n++)
            acc += (g_escore[n] * invd) * value[(size_t)n * HID + t];
    }
    g_s[(size_t)b * HID + t] = acc;
}

__global__ void ln_kernel(const float* __restrict__ x, const float* __restrict__ r,
                          const float* __restrict__ g, const float* __restrict__ b,
                          float* __restrict__ out) {
    int row = blockIdx.x, t = threadIdx.x;
    float v = x[(size_t)row * HID + t] + r[(size_t)row * HID + t];
    float mu = block_sum_256(v) * (1.f / HID);
    float d = v - mu;
    float var = block_sum_256(d * d) * (1.f / HID);
    out[(size_t)row * HID + t] = d * rsqrtf(var + 1e-5f) * g[t] + b[t];
}

// ---------------- launcher ----------------
extern "C" void kernel_launch(void* const* d_in, const int* in_sizes, int n_in,
                              void* d_out, int out_size) {
    const float* smiles   = (const float*)d_in[0];
    const float* key_in   = (const float*)d_in[1];
    const float* value_in = (const float*)d_in[2];
    const int*   batch    = (const int*)  d_in[3];
    const float* wq   = (const float*)d_in[4];
    const float* bq   = (const float*)d_in[5];
    const float* wk   = (const float*)d_in[6];
    const float* bk   = (const float*)d_in[7];
    const float* wv   = (const float*)d_in[8];
    const float* bv   = (const float*)d_in[9];
    const float* ln0g = (const float*)d_in[10];
    const float* ln0b = (const float*)d_in[11];
    const float* ln1g = (const float*)d_in[12];
    const float* ln1b = (const float*)d_in[13];
    const float* w1   = (const float*)d_in[14];
    const float* c1   = (const float*)d_in[15];
    const float* w2   = (const float*)d_in[16];
    const float* c2   = (const float*)d_in[17];

    float* out        = (float*)d_out;
    float* out_smiles = out;
    float* out_att    = out + (size_t)NB * HID;

    float *U, *WkT, *M, *Rv, *S, *Dh, *X1, *H1, *H2;
    cudaGetSymbolAddress((void**)&U,   g_u);
    cudaGetSymbolAddress((void**)&WkT, g_wkT);
    cudaGetSymbolAddress((void**)&M,   g_M);
    cudaGetSymbolAddress((void**)&Rv,  g_rvec);
    cudaGetSymbolAddress((void**)&S,   g_s);
    cudaGetSymbolAddress((void**)&Dh,  g_dh);
    cudaGetSymbolAddress((void**)&X1,  g_x1);
    cudaGetSymbolAddress((void**)&H1,  g_h1);
    cudaGetSymbolAddress((void**)&H2,  g_h2);

    // independent precomputes
    seg_kernel<<<(NB + 1 + 255) / 256, 256>>>(batch);
    transpose_k<<<dim3(HID / 32, HID / 32), dim3(32, 8)>>>(wk, WkT);
    prep_kernel<<<(2 * HID + 1 + 7) / 8, 256>>>(wq, wk, bq, bk);
    c_kernel<<<NB / 8, 256>>>(smiles);

    // M = wq @ wk^T  (small)
    bgemm_kernel<false, false><<<dim3(HID / 64, HID / 128), 256>>>(wq, WkT, nullptr, M, HID, HID, HID);
    // U = smiles @ M + rvec
    bgemm_kernel<true, false><<<dim3(HID / 64, NB / 128), 256>>>(smiles, M, Rv, U, NB, HID, HID);

    // per-node scores, per-graph softmax + weighted value sum
    score_kernel<<<NN / 8, 256>>>(key_in, batch);
    attn_kernel<<<NB, 256>>>(value_in, out_att);

    // Dh = S @ wv + bv
    bgemm_kernel<true, false><<<dim3(HID / 64, NB / 128), 256>>>(S, wv, bv, Dh, NB, HID, HID);
    ln_kernel<<<NB, 256>>>(smiles, Dh, ln0g, ln0b, X1);

    // FFN
    bgemm_kernel<true, true ><<<dim3(HF4 / 64, NB / 128), 256>>>(X1, w1, c1, H1, NB, HF4, HID);
    bgemm_kernel<true, false><<<dim3(HID / 64, NB / 128), 256>>>(H1, w2, c2, H2, NB, HID, HF4);

    ln_kernel<<<NB, 256>>>(X1, H2, ln1g, ln1b, out_smiles);
}